// round 2
// baseline (speedup 1.0000x reference)
#include <cuda_runtime.h>
#include <math.h>

#define NN 100000
#define EE 1600000
#define FIN 64
#define HH 32

// ---------------- device scratch (static, allocation-free) ----------------
__device__ __align__(16) float g_xr[NN * HH];     // transformed features for edge pass (reused)
__device__ __align__(16) float g_agg[NN * HH];    // scatter-add aggregation buffer
__device__ __align__(16) float g_h1[NN * HH];
__device__ __align__(16) float g_h2[NN * HH];
__device__ __align__(16) float g_pvsrc[NN * 2];   // per-node (h2 . Wp_rel, h2 . Wv_rel)
__device__ __align__(16) float g_pvagg[NN * 2];   // aggregated (p, v)
__device__ __align__(16) float g_mask[NN];
__device__ __align__(16) float g_pm[NN];
__device__ unsigned g_maxkey;
__device__ float g_sum;

// ---------------- zeroing ----------------
__global__ void k_zero_all() {
    int i = blockIdx.x * blockDim.x + threadIdx.x;
    float4 z = make_float4(0.f, 0.f, 0.f, 0.f);
    if (i < NN * HH / 4) ((float4*)g_agg)[i] = z;
    if (i < NN / 4)      ((float4*)g_mask)[i] = z;
    if (i < NN * 2 / 4)  ((float4*)g_pvagg)[i] = z;
    if (i == 0) { g_maxkey = 0u; g_sum = 0.f; }
}

__global__ void k_zero_agg() {
    int i = blockIdx.x * blockDim.x + threadIdx.x;
    if (i < NN * HH / 4) ((float4*)g_agg)[i] = make_float4(0.f, 0.f, 0.f, 0.f);
}

// ---------------- xr = x @ Win_rel  (N x 64 -> N x 32) ----------------
__global__ void k_xw64(const float* __restrict__ x, const float* __restrict__ W) {
    __shared__ float sW[FIN * HH];
    for (int i = threadIdx.x; i < FIN * HH; i += blockDim.x) sW[i] = W[i];
    __syncthreads();
    int node = blockIdx.x * blockDim.x + threadIdx.x;
    if (node >= NN) return;
    float acc[HH];
#pragma unroll
    for (int j = 0; j < HH; j++) acc[j] = 0.f;
    const float4* xv = (const float4*)(x + (size_t)node * FIN);
#pragma unroll
    for (int k4 = 0; k4 < FIN / 4; k4++) {
        float4 xk = xv[k4];
        float xs[4] = {xk.x, xk.y, xk.z, xk.w};
#pragma unroll
        for (int kk = 0; kk < 4; kk++) {
            const float4* w4 = (const float4*)(sW + (k4 * 4 + kk) * HH);
#pragma unroll
            for (int j4 = 0; j4 < HH / 4; j4++) {
                float4 w = w4[j4];
                acc[j4 * 4 + 0] += xs[kk] * w.x;
                acc[j4 * 4 + 1] += xs[kk] * w.y;
                acc[j4 * 4 + 2] += xs[kk] * w.z;
                acc[j4 * 4 + 3] += xs[kk] * w.w;
            }
        }
    }
    float4* o = (float4*)(g_xr + (size_t)node * HH);
#pragma unroll
    for (int j4 = 0; j4 < HH / 4; j4++)
        o[j4] = make_float4(acc[j4 * 4], acc[j4 * 4 + 1], acc[j4 * 4 + 2], acc[j4 * 4 + 3]);
}

// ---------------- edge scatter-add of 32-float rows (8 threads / edge) ----------------
__global__ void k_edge32(const int* __restrict__ ei, const float* __restrict__ ew,
                         const int* __restrict__ curp, int do_mask) {
    long long g = (long long)blockIdx.x * blockDim.x + threadIdx.x;
    if (g >= (long long)EE * 8) return;
    int e = (int)(g >> 3);
    int c = (int)(g & 7);
    int s = ei[e];
    int d = ei[EE + e];
    float w = ew[e];
    float4 v = ((const float4*)(g_xr + (size_t)s * HH))[c];
    float* p = g_agg + (size_t)d * HH + c * 4;
    asm volatile("red.global.add.v4.f32 [%0], {%1,%2,%3,%4};"
                 :: "l"(p), "f"(v.x * w), "f"(v.y * w), "f"(v.z * w), "f"(v.w * w)
                 : "memory");
    if (do_mask && c == 0 && s == *curp) g_mask[d] = 1.0f;
}

// ---------------- h1 = relu(agg + bin + x @ Win_root); g_xr = h1 @ Wh_rel ----------------
__global__ void k_node1(const float* __restrict__ x, const float* __restrict__ Wroot,
                        const float* __restrict__ b, const float* __restrict__ Whrel) {
    __shared__ float sWr[FIN * HH];
    __shared__ float sWh[HH * HH];
    __shared__ float sb[HH];
    for (int i = threadIdx.x; i < FIN * HH; i += blockDim.x) sWr[i] = Wroot[i];
    for (int i = threadIdx.x; i < HH * HH; i += blockDim.x) sWh[i] = Whrel[i];
    if (threadIdx.x < HH) sb[threadIdx.x] = b[threadIdx.x];
    __syncthreads();
    int node = blockIdx.x * blockDim.x + threadIdx.x;
    if (node >= NN) return;
    float acc[HH];
    const float4* av = (const float4*)(g_agg + (size_t)node * HH);
#pragma unroll
    for (int j4 = 0; j4 < HH / 4; j4++) {
        float4 a = av[j4];
        acc[j4 * 4 + 0] = a.x + sb[j4 * 4 + 0];
        acc[j4 * 4 + 1] = a.y + sb[j4 * 4 + 1];
        acc[j4 * 4 + 2] = a.z + sb[j4 * 4 + 2];
        acc[j4 * 4 + 3] = a.w + sb[j4 * 4 + 3];
    }
    const float4* xv = (const float4*)(x + (size_t)node * FIN);
#pragma unroll
    for (int k4 = 0; k4 < FIN / 4; k4++) {
        float4 xk = xv[k4];
        float xs[4] = {xk.x, xk.y, xk.z, xk.w};
#pragma unroll
        for (int kk = 0; kk < 4; kk++) {
            const float4* w4 = (const float4*)(sWr + (k4 * 4 + kk) * HH);
#pragma unroll
            for (int j4 = 0; j4 < HH / 4; j4++) {
                float4 w = w4[j4];
                acc[j4 * 4 + 0] += xs[kk] * w.x;
                acc[j4 * 4 + 1] += xs[kk] * w.y;
                acc[j4 * 4 + 2] += xs[kk] * w.z;
                acc[j4 * 4 + 3] += xs[kk] * w.w;
            }
        }
    }
#pragma unroll
    for (int j = 0; j < HH; j++) acc[j] = fmaxf(acc[j], 0.f);
    float4* ho = (float4*)(g_h1 + (size_t)node * HH);
#pragma unroll
    for (int j4 = 0; j4 < HH / 4; j4++)
        ho[j4] = make_float4(acc[j4 * 4], acc[j4 * 4 + 1], acc[j4 * 4 + 2], acc[j4 * 4 + 3]);
    // h1 @ Wh_rel -> g_xr (feeds next edge pass)
    float hr[HH];
#pragma unroll
    for (int j = 0; j < HH; j++) hr[j] = 0.f;
#pragma unroll
    for (int k = 0; k < HH; k++) {
        float hk = acc[k];
        const float4* w4 = (const float4*)(sWh + k * HH);
#pragma unroll
        for (int j4 = 0; j4 < HH / 4; j4++) {
            float4 w = w4[j4];
            hr[j4 * 4 + 0] += hk * w.x;
            hr[j4 * 4 + 1] += hk * w.y;
            hr[j4 * 4 + 2] += hk * w.z;
            hr[j4 * 4 + 3] += hk * w.w;
        }
    }
    float4* ro = (float4*)(g_xr + (size_t)node * HH);
#pragma unroll
    for (int j4 = 0; j4 < HH / 4; j4++)
        ro[j4] = make_float4(hr[j4 * 4], hr[j4 * 4 + 1], hr[j4 * 4 + 2], hr[j4 * 4 + 3]);
}

// ---------------- h2 = relu(agg + bh + h1 @ Wh_root); pvsrc = (h2.Wp_rel, h2.Wv_rel) ----------------
__global__ void k_node2(const float* __restrict__ Whroot, const float* __restrict__ bh,
                        const float* __restrict__ Wp, const float* __restrict__ Wv) {
    __shared__ float sW[HH * HH];
    __shared__ float sb[HH];
    __shared__ float sWp[HH];
    __shared__ float sWv[HH];
    for (int i = threadIdx.x; i < HH * HH; i += blockDim.x) sW[i] = Whroot[i];
    if (threadIdx.x < HH) {
        sb[threadIdx.x] = bh[threadIdx.x];
        sWp[threadIdx.x] = Wp[threadIdx.x];
        sWv[threadIdx.x] = Wv[threadIdx.x];
    }
    __syncthreads();
    int node = blockIdx.x * blockDim.x + threadIdx.x;
    if (node >= NN) return;
    float acc[HH];
    const float4* av = (const float4*)(g_agg + (size_t)node * HH);
#pragma unroll
    for (int j4 = 0; j4 < HH / 4; j4++) {
        float4 a = av[j4];
        acc[j4 * 4 + 0] = a.x + sb[j4 * 4 + 0];
        acc[j4 * 4 + 1] = a.y + sb[j4 * 4 + 1];
        acc[j4 * 4 + 2] = a.z + sb[j4 * 4 + 2];
        acc[j4 * 4 + 3] = a.w + sb[j4 * 4 + 3];
    }
    const float4* hv = (const float4*)(g_h1 + (size_t)node * HH);
#pragma unroll
    for (int k4 = 0; k4 < HH / 4; k4++) {
        float4 hk4 = hv[k4];
        float hs[4] = {hk4.x, hk4.y, hk4.z, hk4.w};
#pragma unroll
        for (int kk = 0; kk < 4; kk++) {
            const float4* w4 = (const float4*)(sW + (k4 * 4 + kk) * HH);
#pragma unroll
            for (int j4 = 0; j4 < HH / 4; j4++) {
                float4 w = w4[j4];
                acc[j4 * 4 + 0] += hs[kk] * w.x;
                acc[j4 * 4 + 1] += hs[kk] * w.y;
                acc[j4 * 4 + 2] += hs[kk] * w.z;
                acc[j4 * 4 + 3] += hs[kk] * w.w;
            }
        }
    }
    float p = 0.f, v = 0.f;
#pragma unroll
    for (int j = 0; j < HH; j++) {
        acc[j] = fmaxf(acc[j], 0.f);
        p += acc[j] * sWp[j];
        v += acc[j] * sWv[j];
    }
    float4* ho = (float4*)(g_h2 + (size_t)node * HH);
#pragma unroll
    for (int j4 = 0; j4 < HH / 4; j4++)
        ho[j4] = make_float4(acc[j4 * 4], acc[j4 * 4 + 1], acc[j4 * 4 + 2], acc[j4 * 4 + 3]);
    *(float2*)(g_pvsrc + (size_t)node * 2) = make_float2(p, v);
}

// ---------------- edge pass for p/v heads: 2 floats/edge ----------------
__global__ void k_edge_pv(const int* __restrict__ ei, const float* __restrict__ ew) {
    int e = blockIdx.x * blockDim.x + threadIdx.x;
    if (e >= EE) return;
    int s = ei[e];
    int d = ei[EE + e];
    float w = ew[e];
    float2 pv = *(const float2*)(g_pvsrc + (size_t)s * 2);
    float* p = g_pvagg + (size_t)d * 2;
    asm volatile("red.global.add.v2.f32 [%0], {%1,%2};"
                 :: "l"(p), "f"(pv.x * w), "f"(pv.y * w) : "memory");
}

// ---------------- finalize p/v, mask, start softmax (max) ----------------
__global__ void k_final_a(const float* __restrict__ Wproot, const float* __restrict__ bp,
                          const float* __restrict__ Wvroot, const float* __restrict__ bv,
                          float* __restrict__ out) {
    __shared__ float sWp[HH];
    __shared__ float sWv[HH];
    if (threadIdx.x < HH) {
        sWp[threadIdx.x] = Wproot[threadIdx.x];
        sWv[threadIdx.x] = Wvroot[threadIdx.x];
    }
    __syncthreads();
    int node = blockIdx.x * blockDim.x + threadIdx.x;
    unsigned key = 0u;
    if (node < NN) {
        float p = g_pvagg[2 * node] + bp[0];
        float v = g_pvagg[2 * node + 1] + bv[0];
        const float4* hv = (const float4*)(g_h2 + (size_t)node * HH);
#pragma unroll
        for (int j4 = 0; j4 < HH / 4; j4++) {
            float4 h = hv[j4];
            p += h.x * sWp[j4 * 4 + 0] + h.y * sWp[j4 * 4 + 1] + h.z * sWp[j4 * 4 + 2] + h.w * sWp[j4 * 4 + 3];
            v += h.x * sWv[j4 * 4 + 0] + h.y * sWv[j4 * 4 + 1] + h.z * sWv[j4 * 4 + 2] + h.w * sWv[j4 * 4 + 3];
        }
        float m = g_mask[node];
        float pm = m * p;
        if (pm == 0.f) pm = __int_as_float(0xFF800000);   // -inf, matching jnp.where(p_m==0, -inf, p_m)
        g_pm[node] = pm;
        out[NN + node] = m * v;
        unsigned bb = __float_as_uint(pm);
        key = (bb & 0x80000000u) ? ~bb : (bb | 0x80000000u);  // order-preserving key, all keys > 0
    }
    unsigned wmax = __reduce_max_sync(0xFFFFFFFFu, key);
    if ((threadIdx.x & 31) == 0 && wmax) atomicMax(&g_maxkey, wmax);
}

// ---------------- softmax exp + sum ----------------
__global__ void k_final_b(float* __restrict__ out) {
    int node = blockIdx.x * blockDim.x + threadIdx.x;
    float e = 0.f;
    if (node < NN) {
        unsigned k = g_maxkey;
        float maxv = __uint_as_float((k & 0x80000000u) ? (k ^ 0x80000000u) : ~k);
        e = expf(g_pm[node] - maxv);
        out[node] = e;
    }
#pragma unroll
    for (int o = 16; o; o >>= 1) e += __shfl_xor_sync(0xFFFFFFFFu, e, o);
    if ((threadIdx.x & 31) == 0 && e != 0.f) atomicAdd(&g_sum, e);
}

// ---------------- softmax normalize ----------------
__global__ void k_final_c(float* __restrict__ out) {
    int node = blockIdx.x * blockDim.x + threadIdx.x;
    if (node < NN) out[node] = out[node] / g_sum;
}

// ---------------- launch ----------------
extern "C" void kernel_launch(void* const* d_in, const int* in_sizes, int n_in,
                              void* d_out, int out_size) {
    const float* x        = (const float*)d_in[0];
    const int*   ei       = (const int*)d_in[1];          // edge_index as int32 (harness dtype)
    const float* ew       = (const float*)d_in[2];
    const int*   cur      = (const int*)d_in[3];
    const float* Win_rel  = (const float*)d_in[4];
    const float* bin_rel  = (const float*)d_in[5];
    const float* Win_root = (const float*)d_in[6];
    const float* Wh_rel   = (const float*)d_in[7];
    const float* bh_rel   = (const float*)d_in[8];
    const float* Wh_root  = (const float*)d_in[9];
    const float* Wp_rel   = (const float*)d_in[10];
    const float* bp_rel   = (const float*)d_in[11];
    const float* Wp_root  = (const float*)d_in[12];
    const float* Wv_rel   = (const float*)d_in[13];
    const float* bv_rel   = (const float*)d_in[14];
    const float* Wv_root  = (const float*)d_in[15];
    float* out = (float*)d_out;

    const int TB = 256;
    const int gz = (NN * HH / 4 + TB - 1) / TB;
    const int gn = (NN + TB - 1) / TB;
    const int ge8 = (int)(((long long)EE * 8 + TB - 1) / TB);
    const int ge = (EE + TB - 1) / TB;

    k_zero_all<<<gz, TB>>>();
    k_xw64<<<gn, TB>>>(x, Win_rel);
    k_edge32<<<ge8, TB>>>(ei, ew, cur, 1);
    k_node1<<<gn, TB>>>(x, Win_root, bin_rel, Wh_rel);
    k_zero_agg<<<gz, TB>>>();
    k_edge32<<<ge8, TB>>>(ei, ew, cur, 0);
    k_node2<<<gn, TB>>>(Wh_root, bh_rel, Wp_rel, Wv_rel);
    k_edge_pv<<<ge, TB>>>(ei, ew);
    k_final_a<<<gn, TB>>>(Wp_root, bp_rel, Wv_root, bv_rel, out);
    k_final_b<<<gn, TB>>>(out);
    k_final_c<<<gn, TB>>>(out);
}